// round 4
// baseline (speedup 1.0000x reference)
#include <cuda_runtime.h>
#include <cuda_bf16.h>

// Gather formulation, v3: spatially-ordered processing.
//   1. grid_build: grid[cell] = row+1 (0 = empty; static zero-init is valid).
//   2. count/scan/emit: stream-compact the grid into (order[j], key[j]) in
//      flat-cell order -> consecutive work items are spatial neighbors, so
//      feats reuse (each row read by <=27 neighboring outputs) hits L1.
//   3. gather_conv: 8 threads per output row, cooperative 27-cell probe via
//      shared memory, register accumulate, one 128B store.
//   4. grid_clear: zero only the N occupied cells (restores invariant).
//
// Inputs: coords[N,3] i32, in_idx/out_idx (unused), in_feats[N,32] f32,
//         kernel[27,32] f32.  Output: [N,32] f32.

#define LGRID 100
#define NCELLS (LGRID * LGRID * LGRID)
#define ROWS_PER_BLOCK 32
#define THREADS_PER_BLOCK 256
#define NB_STRIDE 28
#define MAXN 524288
#define CELLS_PER_BLOCK 1024          // 256 threads * 4 cells (int4)
#define NBLK ((NCELLS + CELLS_PER_BLOCK - 1) / CELLS_PER_BLOCK)   // 977

__device__ int g_grid[NCELLS];        // cell -> row+1, 0 = empty
__device__ int g_order[MAXN];         // j (spatial rank) -> row
__device__ int g_key[MAXN];           // j -> cell index
__device__ int g_blkcnt[1024];        // per-block occupied count
__device__ int g_blkbase[1024];       // exclusive prefix

__global__ void grid_build_kernel(const int* __restrict__ coords, int N) {
    int i = blockIdx.x * blockDim.x + threadIdx.x;
    if (i >= N) return;
    int x = coords[3 * i + 0], y = coords[3 * i + 1], z = coords[3 * i + 2];
    g_grid[(x * LGRID + y) * LGRID + z] = i + 1;
}

__global__ void grid_clear_kernel(const int* __restrict__ coords, int N) {
    int i = blockIdx.x * blockDim.x + threadIdx.x;
    if (i >= N) return;
    int x = coords[3 * i + 0], y = coords[3 * i + 1], z = coords[3 * i + 2];
    g_grid[(x * LGRID + y) * LGRID + z] = 0;
}

__global__ __launch_bounds__(256)
void count_kernel() {
    __shared__ int sred[256];
    int b = blockIdx.x;
    int q = (b * CELLS_PER_BLOCK) / 4 + threadIdx.x;   // int4 index
    int c = 0;
    if (q < NCELLS / 4) {
        int4 v = reinterpret_cast<const int4*>(g_grid)[q];
        c = (v.x != 0) + (v.y != 0) + (v.z != 0) + (v.w != 0);
    }
    sred[threadIdx.x] = c;
    __syncthreads();
    for (int s = 128; s > 0; s >>= 1) {
        if (threadIdx.x < s) sred[threadIdx.x] += sred[threadIdx.x + s];
        __syncthreads();
    }
    if (threadIdx.x == 0) g_blkcnt[b] = sred[0];
}

__global__ __launch_bounds__(1024)
void scan_kernel() {
    __shared__ int s[1024];
    int i = threadIdx.x;
    int v = (i < NBLK) ? g_blkcnt[i] : 0;
    s[i] = v;
    __syncthreads();
    for (int d = 1; d < 1024; d <<= 1) {
        int add = (i >= d) ? s[i - d] : 0;
        __syncthreads();
        s[i] += add;
        __syncthreads();
    }
    if (i < NBLK) g_blkbase[i] = s[i] - v;   // exclusive
}

__global__ __launch_bounds__(256)
void emit_kernel() {
    __shared__ int sscan[256];
    int b = blockIdx.x;
    int q = (b * CELLS_PER_BLOCK) / 4 + threadIdx.x;
    int4 v = make_int4(0, 0, 0, 0);
    int c = 0;
    if (q < NCELLS / 4) {
        v = reinterpret_cast<const int4*>(g_grid)[q];
        c = (v.x != 0) + (v.y != 0) + (v.z != 0) + (v.w != 0);
    }
    sscan[threadIdx.x] = c;
    __syncthreads();
    for (int d = 1; d < 256; d <<= 1) {
        int add = (threadIdx.x >= d) ? sscan[threadIdx.x - d] : 0;
        __syncthreads();
        sscan[threadIdx.x] += add;
        __syncthreads();
    }
    int pos = g_blkbase[b] + sscan[threadIdx.x] - c;   // exclusive within grid
    int cell = q * 4;
    int vals[4] = {v.x, v.y, v.z, v.w};
#pragma unroll
    for (int u = 0; u < 4; u++) {
        if (vals[u] != 0) {
            g_order[pos] = vals[u] - 1;
            g_key[pos] = cell + u;
            pos++;
        }
    }
}

__global__ __launch_bounds__(THREADS_PER_BLOCK)
void gather_conv_kernel(const float4* __restrict__ feats,   // [N, 8] float4
                        const float4* __restrict__ kern,    // [27, 8] float4
                        float4* __restrict__ out,           // [N, 8] float4
                        int N)
{
    __shared__ float4 skern[27 * 8];
    __shared__ int snb[ROWS_PER_BLOCK * NB_STRIDE];

    int tid = threadIdx.x;
    if (tid < 27 * 8) skern[tid] = kern[tid];

    int rl = tid >> 3;
    int g  = tid & 7;
    int j  = blockIdx.x * ROWS_PER_BLOCK + rl;
    bool rowvalid = (j < N);

    int o = 0, cx = 0, cy = 0, cz = 0, cell = 0;
    if (rowvalid) {
        o = g_order[j];
        cell = g_key[j];
        cz = cell % LGRID;
        int t2 = cell / LGRID;
        cy = t2 % LGRID;
        cx = t2 / LGRID;
    }

    // Cooperative probe: thread g handles (dx,dy) pair g; thread 0 also pair 8.
    if (rowvalid) {
        int npairs = (g == 0) ? 2 : 1;
        for (int rep = 0; rep < npairs; rep++) {
            int p = (rep == 0) ? g : 8;
            int dx = p / 3 - 1;
            int dy = p % 3 - 1;
            int nx = cx + dx, ny = cy + dy;
            bool xyok = ((unsigned)nx < LGRID) & ((unsigned)ny < LGRID);
            int base2 = (nx * LGRID + ny) * LGRID + cz;
            int r0 = 0, r1 = 0, r2 = 0;
            if (xyok) {
                if (cz - 1 >= 0)    r0 = g_grid[base2 - 1];
                r1 = g_grid[base2];
                if (cz + 1 < LGRID) r2 = g_grid[base2 + 1];
            }
            int kb = rl * NB_STRIDE + p * 3;
            snb[kb + 0] = r0;
            snb[kb + 1] = r1;
            snb[kb + 2] = r2;
        }
    }
    __syncthreads();

    if (!rowvalid) return;

    float4 acc = make_float4(0.f, 0.f, 0.f, 0.f);
#pragma unroll
    for (int k = 0; k < 27; k++) {
        int enc = snb[rl * NB_STRIDE + k];
        if (enc > 0) {
            float4 f = feats[(long long)(enc - 1) * 8 + g];
            float4 w = skern[k * 8 + g];
            acc.x = fmaf(f.x, w.x, acc.x);
            acc.y = fmaf(f.y, w.y, acc.y);
            acc.z = fmaf(f.z, w.z, acc.z);
            acc.w = fmaf(f.w, w.w, acc.w);
        }
    }

    out[(long long)o * 8 + g] = acc;
}

extern "C" void kernel_launch(void* const* d_in, const int* in_sizes, int n_in,
                              void* d_out, int out_size) {
    const int*    coords = (const int*)d_in[0];
    const float4* feats  = (const float4*)d_in[3];
    const float4* kern   = (const float4*)d_in[4];
    float4*       out    = (float4*)d_out;

    int N = out_size / 32;

    {
        int threads = 256;
        int blocks = (N + threads - 1) / threads;
        grid_build_kernel<<<blocks, threads>>>(coords, N);
    }
    count_kernel<<<NBLK, 256>>>();
    scan_kernel<<<1, 1024>>>();
    emit_kernel<<<NBLK, 256>>>();
    {
        int blocks = (N + ROWS_PER_BLOCK - 1) / ROWS_PER_BLOCK;
        gather_conv_kernel<<<blocks, THREADS_PER_BLOCK>>>(feats, kern, out, N);
    }
    {
        int threads = 256;
        int blocks = (N + threads - 1) / threads;
        grid_clear_kernel<<<blocks, threads>>>(coords, N);
    }
}

// round 5
// speedup vs baseline: 1.1131x; 1.1131x over previous
#include <cuda_runtime.h>
#include <cuda_bf16.h>

// Gather formulation, v4: branchless batched inner loop (MLP=8).
//   1. grid_build: grid[cell] = row+1 (0 = empty; static zero-init valid).
//   2. gather_conv: 8 threads/row. Probe phase compacts the VALID neighbor
//      taps (avg ~8 of 27) into a shared per-row list via a shared atomic
//      counter. Accumulate phase consumes the list in chunks of 8 with
//      unconditional predicate-free LDG.128s (pads select row 0 and a zero
//      weight slot skern[27]), giving 8 loads in flight per thread.
//   3. grid_clear: zero only the N occupied cells.
//
// Inputs: coords[N,3] i32, in_idx/out_idx (unused), in_feats[N,32] f32,
//         kernel[27,32] f32.  Output: [N,32] f32.

#define LGRID 100
#define NCELLS (LGRID * LGRID * LGRID)
#define ROWS_PER_BLOCK 32
#define THREADS_PER_BLOCK 256
#define LIST_STRIDE 28
#define UNROLL 8
#define PADVAL ((1 << 5) | 27)   // row 0, zero-weight slot k=27

__device__ int g_grid[NCELLS];   // cell -> row+1, 0 = empty

__global__ void grid_build_kernel(const int* __restrict__ coords, int N) {
    int i = blockIdx.x * blockDim.x + threadIdx.x;
    if (i >= N) return;
    int x = coords[3 * i + 0], y = coords[3 * i + 1], z = coords[3 * i + 2];
    g_grid[(x * LGRID + y) * LGRID + z] = i + 1;
}

__global__ void grid_clear_kernel(const int* __restrict__ coords, int N) {
    int i = blockIdx.x * blockDim.x + threadIdx.x;
    if (i >= N) return;
    int x = coords[3 * i + 0], y = coords[3 * i + 1], z = coords[3 * i + 2];
    g_grid[(x * LGRID + y) * LGRID + z] = 0;
}

__global__ __launch_bounds__(THREADS_PER_BLOCK)
void gather_conv_kernel(const int* __restrict__ coords,
                        const float4* __restrict__ feats,   // [N, 8] float4
                        const float4* __restrict__ kern,    // [27, 8] float4
                        float4* __restrict__ out,           // [N, 8] float4
                        int N)
{
    __shared__ float4 skern[28 * 8];                 // slot 27 = zeros
    __shared__ int slist[ROWS_PER_BLOCK * LIST_STRIDE];
    __shared__ int scnt[ROWS_PER_BLOCK];

    int tid = threadIdx.x;
    if (tid < 27 * 8) skern[tid] = kern[tid];
    else if (tid < 28 * 8) skern[tid] = make_float4(0.f, 0.f, 0.f, 0.f);
    if (tid < ROWS_PER_BLOCK) scnt[tid] = 0;
    __syncthreads();

    int rl = tid >> 3;   // row within block
    int g  = tid & 7;    // float4 channel group
    int o  = blockIdx.x * ROWS_PER_BLOCK + rl;
    bool rowvalid = (o < N);

    // ---- probe phase: compact valid taps into slist[rl] ----
    if (rowvalid) {
        int cx = coords[3 * o + 0];
        int cy = coords[3 * o + 1];
        int cz = coords[3 * o + 2];
        int npairs = (g == 0) ? 2 : 1;
        for (int rep = 0; rep < npairs; rep++) {
            int p = (rep == 0) ? g : 8;      // (dx,dy) pair index 0..8
            int dx = p / 3 - 1;
            int dy = p % 3 - 1;
            int nx = cx + dx, ny = cy + dy;
            bool xyok = ((unsigned)nx < LGRID) & ((unsigned)ny < LGRID);
            int base2 = (nx * LGRID + ny) * LGRID + cz;
            int r0 = 0, r1 = 0, r2 = 0;
            if (xyok) {
                if (cz - 1 >= 0)    r0 = g_grid[base2 - 1];
                r1 = g_grid[base2];
                if (cz + 1 < LGRID) r2 = g_grid[base2 + 1];
            }
            int kb = p * 3;
            if (r0 > 0) { int pos = atomicAdd(&scnt[rl], 1); slist[rl * LIST_STRIDE + pos] = (r0 << 5) | (kb + 0); }
            if (r1 > 0) { int pos = atomicAdd(&scnt[rl], 1); slist[rl * LIST_STRIDE + pos] = (r1 << 5) | (kb + 1); }
            if (r2 > 0) { int pos = atomicAdd(&scnt[rl], 1); slist[rl * LIST_STRIDE + pos] = (r2 << 5) | (kb + 2); }
        }
    }
    __syncthreads();

    if (!rowvalid) return;

    // ---- accumulate phase: branchless chunks of UNROLL taps ----
    int cnt = scnt[rl];
    const int* mylist = &slist[rl * LIST_STRIDE];

    float4 acc = make_float4(0.f, 0.f, 0.f, 0.f);
    for (int i = 0; i < cnt; i += UNROLL) {
        float4 f[UNROLL];
        float4 w[UNROLL];
#pragma unroll
        for (int u = 0; u < UNROLL; u++) {
            int packed = (i + u < cnt) ? mylist[i + u] : PADVAL;
            int row = (packed >> 5) - 1;
            int k   = packed & 31;
            f[u] = feats[(long long)row * 8 + g];
            w[u] = skern[k * 8 + g];
        }
#pragma unroll
        for (int u = 0; u < UNROLL; u++) {
            acc.x = fmaf(f[u].x, w[u].x, acc.x);
            acc.y = fmaf(f[u].y, w[u].y, acc.y);
            acc.z = fmaf(f[u].z, w[u].z, acc.z);
            acc.w = fmaf(f[u].w, w[u].w, acc.w);
        }
    }

    out[(long long)o * 8 + g] = acc;
}

extern "C" void kernel_launch(void* const* d_in, const int* in_sizes, int n_in,
                              void* d_out, int out_size) {
    const int*    coords = (const int*)d_in[0];
    const float4* feats  = (const float4*)d_in[3];
    const float4* kern   = (const float4*)d_in[4];
    float4*       out    = (float4*)d_out;

    int N = out_size / 32;

    {
        int threads = 256;
        int blocks = (N + threads - 1) / threads;
        grid_build_kernel<<<blocks, threads>>>(coords, N);
    }
    {
        int blocks = (N + ROWS_PER_BLOCK - 1) / ROWS_PER_BLOCK;
        gather_conv_kernel<<<blocks, THREADS_PER_BLOCK>>>(coords, feats, kern, out, N);
    }
    {
        int threads = 256;
        int blocks = (N + threads - 1) / threads;
        grid_clear_kernel<<<blocks, threads>>>(coords, N);
    }
}